// round 6
// baseline (speedup 1.0000x reference)
#include <cuda_runtime.h>
#include <cstdint>

// ---------------------------------------------------------------------------
// Fused SelfAttention (attention over heads axis):
//   qkv = v @ {Wq,Wk,Wv}   (tf32 mma, fp32 accum)
//   per token: attn = softmax((q_h . k_g)/sqrt(32)) over g (8x8), x = attn @ vv
//   out = x @ Wp + bp      (tf32 mma, fp32 accum)
// One CTA = 32 tokens; everything stays in SMEM/registers between stages.
// ---------------------------------------------------------------------------

#define NUM_H   8
#define HD      32
#define DIM     256
#define BT      32      // tokens per CTA
#define NTH     256     // threads per CTA (8 warps)
#define KC      64      // K-chunk rows staged per weight tile

// SMEM strides (in 4-byte elements), chosen for conflict-free fragment loads:
//  STR_VX % 32 == 4  -> A-frag lanes (g*4 + tig) hit distinct banks
//  STR_W  % 32 == 8  -> B-frag lanes (tig*8 + g) hit distinct banks
//  STR_Q  % 32 == 1  -> phase-2 per-lane-token reads hit distinct banks
#define STR_VX  260
#define STR_W   264
#define STR_Q   769

#define OFF_VX  0
#define OFF_W   (BT * STR_VX * 4)            // 33280
#define OFF_Q   (OFF_W + KC * STR_W * 4)     // 33280 + 67584 = 100864
#define SMEM_BYTES (OFF_Q + BT * STR_Q * 4)  // + 98432 = 199296 bytes

__device__ __forceinline__ uint32_t f2tf(float f) {
    uint32_t u;
    asm("cvt.rna.tf32.f32 %0, %1;" : "=r"(u) : "f"(f));
    return u;
}

__device__ __forceinline__ void mma_tf32(float d[4], const uint32_t a[4], const uint32_t b[2]) {
    asm volatile(
        "mma.sync.aligned.m16n8k8.row.col.f32.tf32.tf32.f32 "
        "{%0,%1,%2,%3}, {%4,%5,%6,%7}, {%8,%9}, {%0,%1,%2,%3};"
        : "+f"(d[0]), "+f"(d[1]), "+f"(d[2]), "+f"(d[3])
        : "r"(a[0]), "r"(a[1]), "r"(a[2]), "r"(a[3]), "r"(b[0]), "r"(b[1]));
}

// Stage one [KC x 256] fp32 weight chunk into SMEM as tf32 (coalesced global reads).
__device__ __forceinline__ void stage_w(uint32_t* sW, const float* Wsel, int kc, int tid) {
    const float4* src = reinterpret_cast<const float4*>(Wsel + (size_t)kc * KC * DIM);
    #pragma unroll
    for (int i = 0; i < (KC * DIM / 4) / NTH; ++i) {   // 16 float4 per thread
        int f  = tid + i * NTH;
        int r  = f >> 6;          // row within chunk (256 floats = 64 float4 per row)
        int c4 = f & 63;
        float4 x = src[f];
        uint32_t* dst = sW + r * STR_W + c4 * 4;
        dst[0] = f2tf(x.x); dst[1] = f2tf(x.y); dst[2] = f2tf(x.z); dst[3] = f2tf(x.w);
    }
}

// 8 k-steps (one KC=64 chunk) of m16n8k8 tf32 mma.
// acc[mi][j][4]: mi = m-frag (rows mi*16..mi*16+15), j = n-frag (cols nb+j*8..+7).
__device__ __forceinline__ void mma_chunk(float acc[2][4][4],
                                          const uint32_t* __restrict__ sA,
                                          const uint32_t* __restrict__ sW,
                                          int g, int tig, int nb, int kbase) {
    #pragma unroll
    for (int k8 = 0; k8 < 8; ++k8) {
        int kk = k8 * 8;
        uint32_t a[2][4];
        #pragma unroll
        for (int mi = 0; mi < 2; ++mi) {
            int r = mi * 16 + g;
            int c = kbase + kk + tig;
            a[mi][0] = sA[r * STR_VX + c];
            a[mi][1] = sA[(r + 8) * STR_VX + c];
            a[mi][2] = sA[r * STR_VX + c + 4];
            a[mi][3] = sA[(r + 8) * STR_VX + c + 4];
        }
        #pragma unroll
        for (int j = 0; j < 4; ++j) {
            int n = nb + j * 8 + g;
            uint32_t b[2];
            b[0] = sW[(kk + tig) * STR_W + n];
            b[1] = sW[(kk + tig + 4) * STR_W + n];
            mma_tf32(acc[0][j], a[0], b);
            mma_tf32(acc[1][j], a[1], b);
        }
    }
}

__global__ void __launch_bounds__(NTH)
SelfAttention_695784702010_kernel(const float* __restrict__ v,
                                  const float* __restrict__ Wq,
                                  const float* __restrict__ Wk,
                                  const float* __restrict__ Wv,
                                  const float* __restrict__ Wp,
                                  const float* __restrict__ bp,
                                  float* __restrict__ out) {
    extern __shared__ char smem[];
    uint32_t* sVX  = reinterpret_cast<uint32_t*>(smem + OFF_VX);  // v tile (tf32), later x tile
    uint32_t* sW   = reinterpret_cast<uint32_t*>(smem + OFF_W);   // weight chunk (tf32)
    float*    sQKV = reinterpret_cast<float*>(smem + OFF_Q);      // [32][768] fp32 q|k|vv

    const int tid  = threadIdx.x;
    const int wid  = tid >> 5;
    const int lane = tid & 31;
    const int g    = lane >> 2;   // groupID
    const int tig  = lane & 3;    // thread-in-group

    const size_t rowBase = (size_t)blockIdx.x * BT;
    const float* vBlk = v + rowBase * DIM;

    // ---- Stage v tile [32 x 256] -> tf32 ---------------------------------
    {
        const float4* src = reinterpret_cast<const float4*>(vBlk);
        #pragma unroll
        for (int i = 0; i < (BT * DIM / 4) / NTH; ++i) {   // 8 float4 per thread
            int f  = tid + i * NTH;
            int r  = f >> 6;
            int c4 = f & 63;
            float4 x = src[f];
            uint32_t* dst = sVX + r * STR_VX + c4 * 4;
            dst[0] = f2tf(x.x); dst[1] = f2tf(x.y); dst[2] = f2tf(x.z); dst[3] = f2tf(x.w);
        }
    }
    __syncthreads();

    // ---- Phase 1: qkv = v @ {Wq, Wk, Wv} ---------------------------------
    #pragma unroll 1
    for (int nc = 0; nc < 3; ++nc) {
        const float* Wsel = (nc == 0) ? Wq : (nc == 1) ? Wk : Wv;
        float acc[2][4][4] = {};
        #pragma unroll 1
        for (int kc = 0; kc < 4; ++kc) {
            __syncthreads();                    // previous chunk fully consumed
            stage_w(sW, Wsel, kc, tid);
            __syncthreads();
            mma_chunk(acc, sVX, sW, g, tig, wid * 32, kc * KC);
        }
        // Fragment layout: d0:(g,2t) d1:(g,2t+1) d2:(g+8,2t) d3:(g+8,2t+1)
        #pragma unroll
        for (int mi = 0; mi < 2; ++mi) {
            #pragma unroll
            for (int j = 0; j < 4; ++j) {
                int row = mi * 16 + g;
                int col = nc * 256 + wid * 32 + j * 8 + 2 * tig;
                sQKV[row * STR_Q + col]           = acc[mi][j][0];
                sQKV[row * STR_Q + col + 1]       = acc[mi][j][1];
                sQKV[(row + 8) * STR_Q + col]     = acc[mi][j][2];
                sQKV[(row + 8) * STR_Q + col + 1] = acc[mi][j][3];
            }
        }
    }
    __syncthreads();

    // ---- Phase 2: per-token 8x8 heads-attention --------------------------
    // thread = (head h = wid, token t = lane); softmax is over g within fixed h.
    {
        const int h = wid, t = lane;
        const float* qp = sQKV + t * STR_Q + h * HD;
        const float* kp = sQKV + t * STR_Q + 256;
        const float* vp = sQKV + t * STR_Q + 512;

        float q[HD];
        #pragma unroll
        for (int d = 0; d < HD; ++d) q[d] = qp[d];

        float a[NUM_H];
        float mx = -1e30f;
        #pragma unroll
        for (int gg = 0; gg < NUM_H; ++gg) {
            float s = 0.f;
            #pragma unroll
            for (int d = 0; d < HD; ++d) s += q[d] * kp[gg * HD + d];
            s *= 0.17677669529663687f;   // 1/sqrt(32)
            a[gg] = s;
            mx = fmaxf(mx, s);
        }
        float sum = 0.f;
        #pragma unroll
        for (int gg = 0; gg < NUM_H; ++gg) { a[gg] = __expf(a[gg] - mx); sum += a[gg]; }
        float inv = 1.f / sum;
        #pragma unroll
        for (int gg = 0; gg < NUM_H; ++gg) a[gg] *= inv;

        uint32_t* xp = sVX + t * STR_VX + h * HD;   // reuse v-tile region for x (tf32)
        #pragma unroll
        for (int d = 0; d < HD; ++d) {
            float s = 0.f;
            #pragma unroll
            for (int gg = 0; gg < NUM_H; ++gg) s += a[gg] * vp[gg * HD + d];
            xp[d] = f2tf(s);
        }
    }
    __syncthreads();

    // ---- Phase 3: out = x @ Wp + bp --------------------------------------
    {
        float acc[2][4][4] = {};
        float bias[4][2];
        #pragma unroll
        for (int j = 0; j < 4; ++j) {
            int n = wid * 32 + j * 8 + 2 * tig;
            bias[j][0] = bp[n];
            bias[j][1] = bp[n + 1];
        }
        #pragma unroll 1
        for (int kc = 0; kc < 4; ++kc) {
            __syncthreads();
            stage_w(sW, Wp, kc, tid);
            __syncthreads();
            mma_chunk(acc, sVX, sW, g, tig, wid * 32, kc * KC);
        }

        float* outBlk = out + rowBase * DIM;
        #pragma unroll
        for (int mi = 0; mi < 2; ++mi) {
            #pragma unroll
            for (int j = 0; j < 4; ++j) {
                int row = mi * 16 + g;
                int n = wid * 32 + j * 8 + 2 * tig;
                float2 lo = make_float2(acc[mi][j][0] + bias[j][0],
                                        acc[mi][j][1] + bias[j][1]);
                float2 hi = make_float2(acc[mi][j][2] + bias[j][0],
                                        acc[mi][j][3] + bias[j][1]);
                *reinterpret_cast<float2*>(outBlk + (size_t)row * DIM + n)       = lo;
                *reinterpret_cast<float2*>(outBlk + (size_t)(row + 8) * DIM + n) = hi;
            }
        }
    }
}

extern "C" void kernel_launch(void* const* d_in, const int* in_sizes, int n_in,
                              void* d_out, int out_size) {
    const float* v  = (const float*)d_in[0];
    const float* Wq = (const float*)d_in[1];
    const float* Wk = (const float*)d_in[2];
    const float* Wv = (const float*)d_in[3];
    const float* Wp = (const float*)d_in[4];
    const float* bp = (const float*)d_in[5];
    float* out = (float*)d_out;

    cudaFuncSetAttribute(SelfAttention_695784702010_kernel,
                         cudaFuncAttributeMaxDynamicSharedMemorySize, SMEM_BYTES);

    int M = in_sizes[0] / DIM;          // 65536 tokens
    int grid = M / BT;                  // 2048 CTAs
    SelfAttention_695784702010_kernel<<<grid, NTH, SMEM_BYTES>>>(v, Wq, Wk, Wv, Wp, bp, out);
}